// round 2
// baseline (speedup 1.0000x reference)
#include <cuda_runtime.h>

#define L_ 50
#define T_ 100
#define D_ 64

__device__ __forceinline__ float sigf(float x) {
    return __fdividef(1.0f, 1.0f + __expf(-x));
}

__global__ __launch_bounds__(256) void _HGN_31155692765823_kernel(
    const int* __restrict__ user_ids,
    const int* __restrict__ item_seq_ids,
    const int* __restrict__ target_item_ids,
    const float* __restrict__ user_table,
    const float* __restrict__ item_table,
    const float* __restrict__ W2_table,
    const float* __restrict__ b2_table,
    const float* __restrict__ fg_item_W,
    const float* __restrict__ fg_item_b,
    const float* __restrict__ fg_user_W,
    const float* __restrict__ fg_user_b,
    const float* __restrict__ inst_gate_item,
    const float* __restrict__ inst_gate_user,
    float* __restrict__ out)
{
    __shared__ float Ws[64 * 64];   // Ws[k*64 + d] = fg_item_W[d*64 + k]
    __shared__ float E[L_ * 64];    // gathered item embeddings
    __shared__ float G[L_ * 64];    // gated values
    __shared__ float ue[64], ufg[64], igi[64], v[64];
    __shared__ float t2[L_], inst[L_];
    __shared__ int   sid[L_];
    __shared__ float s_instsum;

    const int b    = blockIdx.x;
    const int tid  = threadIdx.x;
    const int warp = tid >> 5;
    const int lane = tid & 31;
    const int d0   = lane << 1;

    // ---- phase 0: user emb, ids, transposed gate matrix ----
    if (tid < 64) {
        int uid = user_ids[b];
        ue[tid]  = user_table[uid * D_ + tid];
        igi[tid] = inst_gate_item[tid];
    } else if (tid < 64 + L_) {
        sid[tid - 64] = item_seq_ids[b * L_ + (tid - 64)];
    }
    // Ws[i] = fg_item_W[(i&63)*64 + (i>>6)]  (coalesced STS, transposed LDG from hot 16KB table)
    #pragma unroll
    for (int i = tid; i < 4096; i += 256)
        Ws[i] = fg_item_W[((i & 63) << 6) + (i >> 6)];
    __syncthreads();

    // ---- phase 1: gather E + per-user small GEMVs ----
    {
        const float4* it4 = (const float4*)item_table;
        float4* E4w = (float4*)E;
        #pragma unroll
        for (int i = tid; i < L_ * 16; i += 256) {
            int l = i >> 4, c = i & 15;
            E4w[i] = it4[sid[l] * 16 + c];
        }
    }
    if (tid < 64) {
        // ufg[d] = fg_user_b[d] + fg_item_b[d] + sum_k ue[k]*fg_user_W[d][k]
        float acc = fg_user_b[tid] + fg_item_b[tid];
        #pragma unroll
        for (int k = 0; k < 64; k++)
            acc = fmaf(ue[k], fg_user_W[tid * 64 + k], acc);
        ufg[tid] = acc;
    } else if (tid < 64 + L_) {
        int l = tid - 64;
        float acc = 0.f;
        #pragma unroll
        for (int k = 0; k < 64; k++)
            acc = fmaf(ue[k], inst_gate_user[k * L_ + l], acc);
        t2[l] = acc;
    }
    __syncthreads();

    // ---- phase 2: gate GEMM (register tile: 7 rows x 2 cols per lane) ----
    {
        float2 acc[7];
        #pragma unroll
        for (int j = 0; j < 7; j++) acc[j] = make_float2(0.f, 0.f);
        int lrow[7];
        #pragma unroll
        for (int j = 0; j < 7; j++) {
            int l = warp + 8 * j;
            lrow[j] = (l < L_) ? l : (L_ - 1);   // clamped duplicate compute, stores guarded
        }
        const float4* E4 = (const float4*)E;
        #pragma unroll
        for (int k4 = 0; k4 < 16; k4++) {
            float4 e[7];
            #pragma unroll
            for (int j = 0; j < 7; j++) e[j] = E4[lrow[j] * 16 + k4];   // broadcast LDS
            #pragma unroll
            for (int i = 0; i < 4; i++) {
                float2 w = *(const float2*)&Ws[((k4 << 2) + i) * 64 + d0];
                #pragma unroll
                for (int j = 0; j < 7; j++) {
                    float ev = (i == 0) ? e[j].x : (i == 1) ? e[j].y : (i == 2) ? e[j].z : e[j].w;
                    acc[j].x = fmaf(ev, w.x, acc[j].x);
                    acc[j].y = fmaf(ev, w.y, acc[j].y);
                }
            }
        }
        const float bfx = ufg[d0], bfy = ufg[d0 + 1];
        const float gix = igi[d0], giy = igi[d0 + 1];
        #pragma unroll
        for (int j = 0; j < 7; j++) {
            int l = warp + 8 * j;
            if (l >= L_) break;
            float2 ev = *(const float2*)&E[l * 64 + d0];
            float gx = sigf(acc[j].x + bfx) * ev.x;
            float gy = sigf(acc[j].y + bfy) * ev.y;
            *(float2*)&G[l * 64 + d0] = make_float2(gx, gy);
            float p = gx * gix + gy * giy;     // term1 partial
            #pragma unroll
            for (int off = 16; off; off >>= 1)
                p += __shfl_xor_sync(0xffffffffu, p, off);
            if (lane == 0) inst[l] = sigf(p + t2[l]);
        }
    }
    __syncthreads();

    // ---- phase 3: pooling (union, sum_items, inst_sum) ----
    float un = 0.f, si = 0.f;
    if (tid < 64) {
        #pragma unroll
        for (int l = 0; l < L_; l++) {
            un = fmaf(G[l * 64 + tid], inst[l], un);
            si += E[l * 64 + tid];
        }
    } else if (tid < 96) {
        int l = tid - 64;                      // l in [0,32)
        float p = inst[l];
        if (l + 32 < L_) p += inst[l + 32];
        #pragma unroll
        for (int off = 16; off; off >>= 1)
            p += __shfl_xor_sync(0xffffffffu, p, off);
        if (l == 0) s_instsum = p;
    }
    __syncthreads();
    if (tid < 64)
        v[tid] = ue[tid] + __fdividef(un, s_instsum) + si;   // user + union + sum_items
    __syncthreads();

    // ---- phase 4: target scoring: out = b2 + w2 . v ----
    const float vx = v[d0], vy = v[d0 + 1];
    for (int t = warp; t < T_; t += 8) {
        int id = target_item_ids[b * T_ + t];
        float2 w = *(const float2*)&W2_table[id * D_ + d0];
        float p = w.x * vx + w.y * vy;
        #pragma unroll
        for (int off = 16; off; off >>= 1)
            p += __shfl_xor_sync(0xffffffffu, p, off);
        if (lane == 0) out[b * T_ + t] = p + __ldg(&b2_table[id]);
    }
}

extern "C" void kernel_launch(void* const* d_in, const int* in_sizes, int n_in,
                              void* d_out, int out_size) {
    const int B = in_sizes[0];
    _HGN_31155692765823_kernel<<<B, 256>>>(
        (const int*)d_in[0],    // user_ids
        (const int*)d_in[1],    // item_seq_ids
        (const int*)d_in[2],    // target_item_ids
        (const float*)d_in[3],  // user_table
        (const float*)d_in[4],  // item_table
        (const float*)d_in[5],  // W2_table
        (const float*)d_in[6],  // b2_table
        (const float*)d_in[7],  // fg_item_W
        (const float*)d_in[8],  // fg_item_b
        (const float*)d_in[9],  // fg_user_W
        (const float*)d_in[10], // fg_user_b
        (const float*)d_in[11], // inst_gate_item
        (const float*)d_in[12], // inst_gate_user
        (float*)d_out);
}

// round 4
// speedup vs baseline: 3.8010x; 3.8010x over previous
#include <cuda_runtime.h>

#define L_ 50
#define T_ 100
#define D_ 64
#define I_MAX 100000
#define B_MAX 8192
#define WPAD 66   // even pad: rows 8B-aligned for float2 reads, stride mod 32 = 2

// Precomputed scratch (static __device__ arrays — allowed)
__device__ float g_P[I_MAX * D_];        // item_table @ fg_item_W.T
__device__ float g_ufg[B_MAX * D_];      // per-user gate bias term (incl. both biases)
__device__ float g_t2[B_MAX * L_];       // user_emb @ inst_gate_user

__device__ __forceinline__ float sigf(float x) {
    return __fdividef(1.0f, 1.0f + __expf(-x));
}

// ---------------- Kernel 1: P = item_table @ fg_item_W.T ----------------
// 64 rows per CTA, 256 threads. W transposed through padded smem (coalesced LDG).
__global__ __launch_bounds__(256) void k_precompute_P(
    const float* __restrict__ item_table,
    const float* __restrict__ fg_item_W,
    int R)
{
    __shared__ float Wt[64 * WPAD];   // Wt[k*WPAD+d] = W[d*64+k]
    __shared__ float Et[64 * 64];

    const int tid = threadIdx.x, warp = tid >> 5, lane = tid & 31, d0 = lane << 1;

    #pragma unroll
    for (int e = tid; e < 4096; e += 256) {
        int d = e >> 6, k = e & 63;
        Wt[k * WPAD + d] = fg_item_W[e];          // coalesced read, transposed write
    }
    const int r0 = blockIdx.x * 64;
    const float4* it4 = (const float4*)item_table;
    #pragma unroll
    for (int i = tid; i < 64 * 16; i += 256) {
        int r = r0 + (i >> 4);
        if (r >= R) r = R - 1;
        ((float4*)Et)[i] = it4[r * 16 + (i & 15)];
    }
    __syncthreads();

    float2 acc[8];
    #pragma unroll
    for (int j = 0; j < 8; j++) acc[j] = make_float2(0.f, 0.f);
    const float4* E4 = (const float4*)Et;
    const int rb = warp * 8;
    #pragma unroll
    for (int k4 = 0; k4 < 16; k4++) {
        float4 e[8];
        #pragma unroll
        for (int j = 0; j < 8; j++) e[j] = E4[(rb + j) * 16 + k4];     // broadcast LDS
        #pragma unroll
        for (int i = 0; i < 4; i++) {
            float2 w = *(const float2*)&Wt[((k4 << 2) + i) * WPAD + d0]; // aligned, conflict-free
            #pragma unroll
            for (int j = 0; j < 8; j++) {
                float ev = (i == 0) ? e[j].x : (i == 1) ? e[j].y : (i == 2) ? e[j].z : e[j].w;
                acc[j].x = fmaf(ev, w.x, acc[j].x);
                acc[j].y = fmaf(ev, w.y, acc[j].y);
            }
        }
    }
    #pragma unroll
    for (int j = 0; j < 8; j++) {
        int r = r0 + rb + j;
        if (r < R) *(float2*)&g_P[r * 64 + d0] = acc[j];
    }
}

// ---------------- Kernel 2: per-user ufg and t2 ----------------
// 32 users per CTA; fg_user_W transposed through smem once per CTA.
__global__ __launch_bounds__(256) void k_user(
    const int* __restrict__ user_ids,
    const float* __restrict__ user_table,
    const float* __restrict__ fg_user_W,
    const float* __restrict__ fg_item_b,
    const float* __restrict__ fg_user_b,
    const float* __restrict__ inst_gate_user,
    int B)
{
    __shared__ float Wt[64 * WPAD];
    __shared__ float IG[64 * L_];
    __shared__ float UE[32 * 64];
    __shared__ float bs[64];
    __shared__ int   uids[32];

    const int tid = threadIdx.x;
    #pragma unroll
    for (int e = tid; e < 4096; e += 256) {
        int d = e >> 6, k = e & 63;
        Wt[k * WPAD + d] = fg_user_W[e];
    }
    for (int e = tid; e < 64 * L_; e += 256) IG[e] = inst_gate_user[e];
    if (tid < 64) bs[tid] = fg_item_b[tid] + fg_user_b[tid];
    const int u0 = blockIdx.x * 32;
    if (tid < 32) {
        int u = u0 + tid;
        uids[tid] = (u < B) ? user_ids[u] : user_ids[0];
    }
    __syncthreads();
    const float4* ut4 = (const float4*)user_table;
    #pragma unroll
    for (int i = tid; i < 32 * 16; i += 256)
        ((float4*)UE)[i] = ut4[uids[i >> 4] * 16 + (i & 15)];
    __syncthreads();

    // ufg: thread = (user-group, d); 64 threads share a user -> UE broadcast
    const int d = tid & 63, ug = tid >> 6;
    for (int uu = ug; uu < 32; uu += 4) {
        float acc = bs[d];
        #pragma unroll
        for (int k = 0; k < 64; k++)
            acc = fmaf(UE[uu * 64 + k], Wt[k * WPAD + d], acc);
        int u = u0 + uu;
        if (u < B) g_ufg[u * 64 + d] = acc;
    }
    // t2
    for (int idx = tid; idx < 32 * L_; idx += 256) {
        int uu = idx / L_, l = idx - uu * L_;
        float acc = 0.f;
        #pragma unroll
        for (int k = 0; k < 64; k++)
            acc = fmaf(UE[uu * 64 + k], IG[k * L_ + l], acc);
        int u = u0 + uu;
        if (u < B) g_t2[u * L_ + l] = acc;
    }
}

// ---------------- Kernel 3: main (gather + pointwise + scoring) ----------------
__global__ __launch_bounds__(256) void k_main(
    const int* __restrict__ user_ids,
    const int* __restrict__ item_seq_ids,
    const int* __restrict__ target_item_ids,
    const float* __restrict__ user_table,
    const float* __restrict__ item_table,
    const float* __restrict__ W2_table,
    const float* __restrict__ b2_table,
    const float* __restrict__ inst_gate_item,
    float* __restrict__ out)
{
    __shared__ int   sid[L_];
    __shared__ float uf[64], t2s[L_];
    __shared__ float UNs[8 * 64], SIs[8 * 64], ISs[8];
    __shared__ float v[64];
    __shared__ float s_is;

    const int b = blockIdx.x;
    const int tid = threadIdx.x, warp = tid >> 5, lane = tid & 31, d0 = lane << 1;

    if (tid < L_)                    sid[tid]       = item_seq_ids[b * L_ + tid];
    else if (tid >= 64 && tid < 128) uf[tid - 64]   = g_ufg[b * 64 + (tid - 64)];
    else if (tid >= 128 && tid < 128 + L_) t2s[tid - 128] = g_t2[b * L_ + (tid - 128)];
    __syncthreads();

    const float2 gi = *(const float2*)&inst_gate_item[d0];
    const float ufx = uf[d0], ufy = uf[d0 + 1];
    float2 un = make_float2(0.f, 0.f), si = make_float2(0.f, 0.f);
    float isum = 0.f;

    for (int l = warp; l < L_; l += 8) {
        const int id = sid[l];
        float2 p = *(const float2*)&g_P[id * 64 + d0];
        float2 e = *(const float2*)&item_table[id * 64 + d0];
        float gx = sigf(p.x + ufx) * e.x;
        float gy = sigf(p.y + ufy) * e.y;
        float t1 = gx * gi.x + gy * gi.y;
        #pragma unroll
        for (int off = 16; off; off >>= 1)
            t1 += __shfl_xor_sync(0xffffffffu, t1, off);
        float inst = sigf(t1 + t2s[l]);
        un.x = fmaf(gx, inst, un.x);
        un.y = fmaf(gy, inst, un.y);
        si.x += e.x;  si.y += e.y;
        isum += inst;
    }
    *(float2*)&UNs[warp * 64 + d0] = un;
    *(float2*)&SIs[warp * 64 + d0] = si;
    if (lane == 0) ISs[warp] = isum;
    __syncthreads();

    float a = 0.f, s = 0.f;
    if (tid < 64) {
        #pragma unroll
        for (int w = 0; w < 8; w++) { a += UNs[w * 64 + tid]; s += SIs[w * 64 + tid]; }
    } else if (tid == 64) {
        float q = 0.f;
        #pragma unroll
        for (int w = 0; w < 8; w++) q += ISs[w];
        s_is = q;
    }
    __syncthreads();
    if (tid < 64) {
        int uid = user_ids[b];
        v[tid] = user_table[uid * 64 + tid] + __fdividef(a, s_is) + s;
    }
    __syncthreads();

    const float vx = v[d0], vy = v[d0 + 1];
    for (int t = warp; t < T_; t += 8) {
        int id = target_item_ids[b * T_ + t];
        float2 w = *(const float2*)&W2_table[id * 64 + d0];
        float p = w.x * vx + w.y * vy;
        #pragma unroll
        for (int off = 16; off; off >>= 1)
            p += __shfl_xor_sync(0xffffffffu, p, off);
        if (lane == 0) out[b * T_ + t] = p + __ldg(&b2_table[id]);
    }
}

extern "C" void kernel_launch(void* const* d_in, const int* in_sizes, int n_in,
                              void* d_out, int out_size) {
    const int B = in_sizes[0] > B_MAX ? B_MAX : in_sizes[0];
    int R = in_sizes[4] / D_;
    if (R > I_MAX) R = I_MAX;

    k_precompute_P<<<(R + 63) / 64, 256>>>(
        (const float*)d_in[4], (const float*)d_in[7], R);

    k_user<<<(B + 31) / 32, 256>>>(
        (const int*)d_in[0], (const float*)d_in[3], (const float*)d_in[9],
        (const float*)d_in[8], (const float*)d_in[10], (const float*)d_in[12], B);

    k_main<<<B, 256>>>(
        (const int*)d_in[0], (const int*)d_in[1], (const int*)d_in[2],
        (const float*)d_in[3], (const float*)d_in[4], (const float*)d_in[5],
        (const float*)d_in[6], (const float*)d_in[11], (float*)d_out);
}